// round 17
// baseline (speedup 1.0000x reference)
#include <cuda_runtime.h>
#include <cuda_bf16.h>

// LocalMGDCF: out = BETA*x + sum_{k=1..4} ALPHA^k (P^k x),  P = D^-1 A (mean-aggr).
// ZERO __device__ globals. CSR (cursor+col+spare) packed into cols 112..127 of
// nodes 0..49999 inside d_out. One persistent kernel; software grid barrier.
// In-place chunked Horner (16 cols/chunk, 2-phase hops); chunk 7 iterates in
// region 6 before chunk 6, finals deferred in registers, written over CSR last.
// R15: two threads/node (8 cols each). R16: bf16 iterates (one 16B gather/thread).
// R17: NBLK=444 (3 blocks on every SM; balanced per-block node ranges) +
// depth-2 software-pipelined gathers (MLP 2).

#define NN 100000
#define EE 600000
#define ALPHA_C 0.1f
#define BETA_C 0.9f

#define TPB 512
#define NBLK 444                            // 148 SMs * 3 co-resident blocks
#define COL_BASE   NN                       // csr-space index of col[] start
#define SPARE_BASE 700000                   // cnt, gen
#define AUX_BASE   (SPARE_BASE + 8)         // per-block scan totals (NBLK words)

// csr-space word i -> word index into d_out (int view). Region = cols 112..127
// of nodes 0..49999.
__device__ __forceinline__ int csr_word(int i) {
    return ((i >> 4) * 128) + 112 + (i & 15);
}

__device__ __forceinline__ int eidx(const void* p, int e, bool is64) {
    int v = is64 ? (int)((const long long*)p)[e] : ((const int*)p)[e];
    return min(max(v, 0), NN - 1);   // clamp: all downstream accesses in-bounds
}

// simple software grid barrier (all blocks co-resident by construction)
__device__ __forceinline__ void gbar(int* oi) {
    __syncthreads();
    if (threadIdx.x == 0) {
        int* cnt = &oi[csr_word(SPARE_BASE)];
        volatile int* gen = (volatile int*)&oi[csr_word(SPARE_BASE + 1)];
        __threadfence();
        int g = *gen;
        if (atomicAdd(cnt, 1) == NBLK - 1) {
            atomicExch(cnt, 0);
            __threadfence();
            atomicAdd((int*)gen, 1);
        } else {
            while (*gen == g) __nanosleep(64);
        }
        __threadfence();
    }
    __syncthreads();
}

__global__ void init_kernel(float* out) {
    int* oi = (int*)out;
    if (threadIdx.x < 8) oi[csr_word(SPARE_BASE + (int)threadIdx.x)] = 0;
}

__global__ __launch_bounds__(TPB, 3)
void mgdcf_kernel(const float* __restrict__ x, const void* __restrict__ src,
                  const void* __restrict__ dst, float* out)
{
    int* oi = (int*)out;
    const int T = NBLK * TPB;                 // 227328
    const int t = blockIdx.x * TPB + threadIdx.x;

    // dtype probe: redundant per-thread. int64 indices < 1e5 have all-zero
    // high words; int32 -> odd words are random values.
    const unsigned* sw = (const unsigned*)src;
    unsigned pv = 0;
    #pragma unroll
    for (int q = 0; q < 8; q++) pv |= __ldg(&sw[2 * q + 1]);
    const bool is64 = (pv == 0u);

    // ---- CSR build ----
    for (int i = t; i < NN; i += T) oi[csr_word(i)] = 0;          // deg := 0
    gbar(oi);

    for (int e = t; e < EE; e += T)                               // histogram
        atomicAdd(&oi[csr_word(eidx(dst, e, is64))], 1);
    gbar(oi);

    // exclusive scan (blocked: thread t owns node t; high blocks idle here)
    __shared__ int wsum[16];
    __shared__ int sbase;
    const int lane = threadIdx.x & 31, wid = threadIdx.x >> 5;
    int v = (t < NN) ? __ldcg((const int*)&oi[csr_word(t)]) : 0;
    int incl = v;
    #pragma unroll
    for (int o = 1; o < 32; o <<= 1) {
        int tt = __shfl_up_sync(~0u, incl, o);
        if (lane >= o) incl += tt;
    }
    if (lane == 31) wsum[wid] = incl;
    __syncthreads();
    if (wid == 0) {
        int ws = (lane < 16) ? wsum[lane] : 0;
        #pragma unroll
        for (int o = 1; o < 16; o <<= 1) {
            int tt = __shfl_up_sync(~0u, ws, o);
            if (lane >= o) ws += tt;
        }
        if (lane < 16) wsum[lane] = ws;
    }
    __syncthreads();
    incl += wid ? wsum[wid - 1] : 0;
    if (threadIdx.x == 0) oi[csr_word(AUX_BASE + blockIdx.x)] = wsum[15];
    gbar(oi);
    {
        int part = 0;
        for (int j = threadIdx.x; j < blockIdx.x; j += TPB)
            part += __ldcg((const int*)&oi[csr_word(AUX_BASE + j)]);
        #pragma unroll
        for (int o = 16; o > 0; o >>= 1) part += __shfl_xor_sync(~0u, part, o);
        __syncthreads();              // wsum reuse
        if (lane == 0) wsum[wid] = part;
        __syncthreads();
        if (threadIdx.x == 0) {
            int s2 = 0;
            #pragma unroll
            for (int q = 0; q < 16; q++) s2 += wsum[q];
            sbase = s2;
        }
        __syncthreads();
    }
    if (t < NN) oi[csr_word(t)] = sbase + incl - v;               // cursor=rowptr
    gbar(oi);

    for (int e = t; e < EE; e += T) {                             // fill
        int d = eidx(dst, e, is64);
        int s = eidx(src, e, is64);
        int p = atomicAdd(&oi[csr_word(d)], 1);
        oi[csr_word(COL_BASE + p)] = s;
    }
    gbar(oi);

    // ---- hop engine: balanced per-block node range, 2 threads/node ----
    const int nstart = (int)(((long long)blockIdx.x * NN) / NBLK);
    const int nend   = (int)(((long long)(blockIdx.x + 1) * NN) / NBLK);
    const int node   = nstart + (int)(threadIdx.x >> 1);   // <= 226 nodes/block
    const int hf     = threadIdx.x & 1;
    const bool has   = (node < nend);

    int rs = 0, re = 0;
    float ainv = 0.f;
    if (has) {
        re = __ldcg((const int*)&oi[csr_word(node)]);
        rs = node ? __ldcg((const int*)&oi[csr_word(node - 1)]) : 0;
        int dg = re - rs;
        ainv = (dg > 0) ? (ALPHA_C / (float)dg) : 0.f;
    }

    float def[8];
    #pragma unroll
    for (int q = 0; q < 8; q++) def[q] = 0.f;

    // chunk order: 0..5, 7 (h-iterate in region 6), 6 (in-place, last)
    #pragma unroll 1
    for (int ci = 0; ci < 8; ci++) {
        const int c  = (ci < 6) ? ci : (ci == 6 ? 7 : 6);
        const int hb = (c == 7) ? 6 : c;
        #pragma unroll 1
        for (int k = 1; k <= 4; k++) {
            float acc[8];
            #pragma unroll
            for (int q = 0; q < 8; q++) acc[q] = 0.f;
            if (has && rs < re) {
                if (k == 1) {
                    // fp32 x gather, depth-2 pipeline (2x16B per neighbor)
                    const float4* G = ((const float4*)x) + c * 4 + hf * 2;
                    int s0 = __ldg((const int*)&oi[csr_word(COL_BASE + rs)]);
                    float4 a0 = __ldg(G + (size_t)s0 * 32 + 0);
                    float4 a1 = __ldg(G + (size_t)s0 * 32 + 1);
                    for (int j = rs; j < re; j++) {
                        float4 b0, b1;
                        if (j + 1 < re) {
                            int s1 = __ldg((const int*)&oi[csr_word(COL_BASE + j + 1)]);
                            b0 = __ldg(G + (size_t)s1 * 32 + 0);
                            b1 = __ldg(G + (size_t)s1 * 32 + 1);
                        }
                        acc[0] += a0.x; acc[1] += a0.y; acc[2] += a0.z; acc[3] += a0.w;
                        acc[4] += a1.x; acc[5] += a1.y; acc[6] += a1.z; acc[7] += a1.w;
                        a0 = b0; a1 = b1;
                    }
                } else {
                    // bf16 iterate gather, depth-2 pipeline (1x16B per neighbor)
                    const uint4* Gb = ((const uint4*)out) + hb * 4 + hf;
                    int s0 = __ldg((const int*)&oi[csr_word(COL_BASE + rs)]);
                    uint4 u = __ldcg(Gb + (size_t)s0 * 32);
                    for (int j = rs; j < re; j++) {
                        uint4 un;
                        if (j + 1 < re) {
                            int s1 = __ldg((const int*)&oi[csr_word(COL_BASE + j + 1)]);
                            un = __ldcg(Gb + (size_t)s1 * 32);
                        }
                        __nv_bfloat162 b0 = *reinterpret_cast<__nv_bfloat162*>(&u.x);
                        __nv_bfloat162 b1 = *reinterpret_cast<__nv_bfloat162*>(&u.y);
                        __nv_bfloat162 b2 = *reinterpret_cast<__nv_bfloat162*>(&u.z);
                        __nv_bfloat162 b3 = *reinterpret_cast<__nv_bfloat162*>(&u.w);
                        float2 f0 = __bfloat1622float2(b0);
                        float2 f1 = __bfloat1622float2(b1);
                        float2 f2 = __bfloat1622float2(b2);
                        float2 f3 = __bfloat1622float2(b3);
                        acc[0] += f0.x; acc[1] += f0.y; acc[2] += f1.x; acc[3] += f1.y;
                        acc[4] += f2.x; acc[5] += f2.y; acc[6] += f3.x; acc[7] += f3.y;
                        u = un;
                    }
                }
            }
            // barrier before writing iff write region == gather region
            if ((k == 2) || (k == 3) || (k == 4 && c != 7)) gbar(oi);
            if (has) {
                const float cx = (k == 4) ? BETA_C : 1.0f;
                const float4* xr = ((const float4*)x) + (size_t)node * 32 + c * 4 + hf * 2;
                float4 x0 = __ldg(xr + 0), x1 = __ldg(xr + 1);
                float vv[8];
                vv[0] = cx * x0.x + ainv * acc[0];
                vv[1] = cx * x0.y + ainv * acc[1];
                vv[2] = cx * x0.z + ainv * acc[2];
                vv[3] = cx * x0.w + ainv * acc[3];
                vv[4] = cx * x1.x + ainv * acc[4];
                vv[5] = cx * x1.y + ainv * acc[5];
                vv[6] = cx * x1.z + ainv * acc[6];
                vv[7] = cx * x1.w + ainv * acc[7];

                if (k < 4) {
                    // store bf16 iterate: 16B per thread, lower half of region hb
                    __nv_bfloat162 c0 = __float22bfloat162_rn(make_float2(vv[0], vv[1]));
                    __nv_bfloat162 c1 = __float22bfloat162_rn(make_float2(vv[2], vv[3]));
                    __nv_bfloat162 c2 = __float22bfloat162_rn(make_float2(vv[4], vv[5]));
                    __nv_bfloat162 c3 = __float22bfloat162_rn(make_float2(vv[6], vv[7]));
                    uint4 u;
                    u.x = *reinterpret_cast<unsigned*>(&c0);
                    u.y = *reinterpret_cast<unsigned*>(&c1);
                    u.z = *reinterpret_cast<unsigned*>(&c2);
                    u.w = *reinterpret_cast<unsigned*>(&c3);
                    ((uint4*)out)[(size_t)node * 32 + hb * 4 + hf] = u;
                } else if (c == 7 && node < 50000) {
                    #pragma unroll
                    for (int q = 0; q < 8; q++) def[q] = vv[q];   // defer over CSR
                } else {
                    float4* w = ((float4*)out) + (size_t)node * 32 + c * 4 + hf * 2;
                    w[0] = make_float4(vv[0], vv[1], vv[2], vv[3]);
                    w[1] = make_float4(vv[4], vv[5], vv[6], vv[7]);
                }
            }
            if (!(c == 6 && k == 4)) gbar(oi);   // last phase: no barrier
        }
    }

    // final: deferred chunk-7 outputs overwrite the CSR. Safe: the last CSR
    // reads happen in the chunk-6 k=4 gather, which completes before that
    // phase's pre-write barrier, which precedes this store.
    if (has && node < 50000) {
        float4* w = ((float4*)out) + (size_t)node * 32 + 28 + hf * 2;
        w[0] = make_float4(def[0], def[1], def[2], def[3]);
        w[1] = make_float4(def[4], def[5], def[6], def[7]);
    }
}

extern "C" void kernel_launch(void* const* d_in, const int* in_sizes, int n_in,
                              void* d_out, int out_size) {
    const float* x   = (const float*)d_in[0];
    const void*  src = d_in[1];
    const void*  dst = d_in[2];
    float*       out = (float*)d_out;
    (void)in_sizes; (void)n_in; (void)out_size;

    init_kernel<<<1, 32>>>(out);
    mgdcf_kernel<<<NBLK, TPB>>>(x, src, dst, out);
}